// round 11
// baseline (speedup 1.0000x reference)
#include <cuda_runtime.h>
#include <cuda_fp16.h>

#define F_IN  14
#define HEADS 8
#define DIM   8
#define F1    64          // HEADS*DIM
#define NEG   0.2f
#define MAXN  100000
#define MAXE  1600000
#define TILE  1024
#define MAXT  ((MAXN + TILE - 1) / TILE)

// ------------------------- scratch (device globals; no allocs) -------------
__device__ __half   g_h1h[MAXN * F1];   // layer1 linear output, fp16 [N,64]
__device__ float    g_as1 [MAXN * HEADS];
__device__ float    g_ad1 [MAXN * HEADS];
__device__ unsigned g_p2  [MAXN * 8];   // packed layer2 record: w0..3 = 8 fp16 h2, w4 = fp32 as2
__device__ float    g_ad2 [MAXN];
__device__ int      g_ssrc[MAXE];       // src ids sorted by dst (CSR col idx)
__device__ int      g_cnt [MAXN];
__device__ int      g_off [MAXN + 1];
__device__ int      g_cur [MAXN];
__device__ int      g_bsum[MAXT];
__device__ int      g_bpre[MAXT];
__device__ int      g_is64;

// ------------------------- helpers ----------------------------------------
__device__ __forceinline__ float lrelu(float x) { return x > 0.f ? x : NEG * x; }

__device__ __forceinline__ void acc8h(const uint4 u, float w, float4& a0, float4& a1) {
    float2 p0 = __half22float2(*(const __half2*)&u.x);
    float2 p1 = __half22float2(*(const __half2*)&u.y);
    float2 p2 = __half22float2(*(const __half2*)&u.z);
    float2 p3 = __half22float2(*(const __half2*)&u.w);
    a0.x += p0.x * w; a0.y += p0.y * w; a0.z += p1.x * w; a0.w += p1.y * w;
    a1.x += p2.x * w; a1.y += p2.y * w; a1.z += p3.x * w; a1.w += p3.y * w;
}

// ------------------------- CSR build ---------------------------------------
// zero histogram + (block 0) edge dtype detect
__global__ void k_zero(const unsigned long long* p, int n) {
    int i = blockIdx.x * blockDim.x + threadIdx.x;
    if (i < n) g_cnt[i] = 0;
    if (blockIdx.x == 0 && threadIdx.x == 0) {
        int is64 = 1;
        for (int k = 0; k < 64; k++)
            if (p[k] >> 32) { is64 = 0; break; }
        g_is64 = is64;
    }
}

__global__ void k_hist(const void* ei, int e) {
    int i = blockIdx.x * blockDim.x + threadIdx.x;
    if (i >= e) return;
    int d = g_is64 ? (int)((const long long*)ei)[e + i]
                   : ((const int*)ei)[e + i];
    atomicAdd(&g_cnt[d], 1);
}

__global__ void __launch_bounds__(256) k_tilesum(int n) {
    __shared__ int sw[8];
    int base = blockIdx.x * TILE;
    int t = threadIdx.x;
    int s = 0;
#pragma unroll
    for (int k = 0; k < 4; k++) {
        int i = base + t * 4 + k;
        if (i < n) s += g_cnt[i];
    }
#pragma unroll
    for (int m = 16; m; m >>= 1) s += __shfl_xor_sync(0xffffffffu, s, m);
    if ((t & 31) == 0) sw[t >> 5] = s;
    __syncthreads();
    if (t == 0) {
        int tot = 0;
#pragma unroll
        for (int w = 0; w < 8; w++) tot += sw[w];
        g_bsum[blockIdx.x] = tot;
    }
}

__global__ void __launch_bounds__(128) k_scanb(int ntiles, int n, int e) {
    __shared__ int sp[128];
    int t = threadIdx.x;
    int v = (t < ntiles) ? g_bsum[t] : 0;
    sp[t] = v;
    __syncthreads();
#pragma unroll
    for (int off = 1; off < 128; off <<= 1) {
        int u = (t >= off) ? sp[t - off] : 0;
        __syncthreads();
        sp[t] += u;
        __syncthreads();
    }
    if (t < ntiles) g_bpre[t] = sp[t] - v;
    if (t == 0) g_off[n] = e;
}

__global__ void __launch_bounds__(256) k_offsets(int n) {
    __shared__ int sp[256];
    int base = blockIdx.x * TILE;
    int t = threadIdx.x;
    int v[4]; int s = 0;
#pragma unroll
    for (int k = 0; k < 4; k++) {
        int i = base + t * 4 + k;
        v[k] = (i < n) ? g_cnt[i] : 0;
        s += v[k];
    }
    sp[t] = s;
    __syncthreads();
#pragma unroll
    for (int off = 1; off < 256; off <<= 1) {
        int u = (t >= off) ? sp[t - off] : 0;
        __syncthreads();
        sp[t] += u;
        __syncthreads();
    }
    int run = g_bpre[blockIdx.x] + sp[t] - s;
#pragma unroll
    for (int k = 0; k < 4; k++) {
        int i = base + t * 4 + k;
        if (i < n) { g_off[i] = run; g_cur[i] = run; run += v[k]; }
    }
}

__global__ void k_scatter(const void* ei, int e) {
    int i = blockIdx.x * blockDim.x + threadIdx.x;
    if (i >= e) return;
    int s, d;
    if (g_is64) {
        const long long* p = (const long long*)ei;
        s = (int)p[i]; d = (int)p[e + i];
    } else {
        const int* p = (const int*)ei;
        s = p[i]; d = p[e + i];
    }
    int pos = atomicAdd(&g_cur[d], 1);
    g_ssrc[pos] = s;
}

// ------------------------- layer 1: fused gemm + logits --------------------
__global__ void __launch_bounds__(256) k_l1(const float* __restrict__ x,
                                            const float* __restrict__ W1,
                                            const float* __restrict__ asrc,
                                            const float* __restrict__ adst, int n) {
    __shared__ float sW[F_IN * F1];
    __shared__ float sS[F1], sD[F1];
    int tid = threadIdx.x;
    for (int i = tid; i < F_IN * F1; i += 256) sW[i] = W1[i];
    if (tid < F1) { sS[tid] = asrc[tid]; sD[tid] = adst[tid]; }
    __syncthreads();

    int node = blockIdx.x * 4 + (tid >> 6);
    int c = tid & 63;
    if (node >= n) return;

    const float* xr = x + node * F_IN;
    float acc = 0.f;
#pragma unroll
    for (int k = 0; k < F_IN; k++) acc += xr[k] * sW[k * F1 + c];
    g_h1h[node * F1 + c] = __float2half_rn(acc);

    float as = acc * sS[c], ad = acc * sD[c];
#pragma unroll
    for (int m = 1; m < 8; m <<= 1) {
        as += __shfl_xor_sync(0xffffffffu, as, m, 8);
        ad += __shfl_xor_sync(0xffffffffu, ad, m, 8);
    }
    if ((c & 7) == 0) {
        int j = node * HEADS + (c >> 3);
        g_as1[j] = as;
        g_ad1[j] = ad;
    }
}

// --------- layer 1 gather + normalize + ELU + FUSED layer 2 gemm/logits ----
// 8 threads per node. After the gather epilogue, the 8-thread group holds the
// node's full 64-dim vector in registers -> compute h2 = hL2@W2 via partials
// + 8-lane reduction, emit packed layer2 record. No g_hL2 round-trip, no k_l2.
__global__ void __launch_bounds__(256) k_gather1l2(const float* __restrict__ b1,
                                                   const float* __restrict__ W2,
                                                   const float* __restrict__ asrc2,
                                                   const float* __restrict__ adst2,
                                                   int n) {
    __shared__ float sW2[F1 * DIM], sS2[DIM], sD2[DIM];
    int tid = threadIdx.x;
    for (int i = tid; i < F1 * DIM; i += 256) sW2[i] = W2[i];
    if (tid < DIM) { sS2[tid] = asrc2[tid]; sD2[tid] = adst2[tid]; }
    __syncthreads();

    int node = blockIdx.x * 32 + (tid >> 3);
    int h = tid & 7;
    if (node >= n) return;                 // whole 8-lane segments exit together

    int beg = g_off[node], end = g_off[node + 1];
    float ad = g_ad1[node * 8 + h];

    float4 acc0 = make_float4(0.f, 0.f, 0.f, 0.f);
    float4 acc1 = make_float4(0.f, 0.f, 0.f, 0.f);

    float wl = __expf(lrelu(g_as1[node * 8 + h] + ad));
    acc8h(*(const uint4*)(g_h1h + node * F1 + h * 8), wl, acc0, acc1);
    float ws = wl;

    int j = beg;
    for (; j + 1 < end; j += 2) {
        int s0 = g_ssrc[j], s1 = g_ssrc[j + 1];
        float e0 = g_as1[s0 * 8 + h], e1 = g_as1[s1 * 8 + h];
        uint4 u = *(const uint4*)(g_h1h + s0 * F1 + h * 8);
        uint4 v = *(const uint4*)(g_h1h + s1 * F1 + h * 8);
        float w0 = __expf(lrelu(e0 + ad));
        float w1 = __expf(lrelu(e1 + ad));
        acc8h(u, w0, acc0, acc1);
        acc8h(v, w1, acc0, acc1);
        ws += w0 + w1;
    }
    if (j < end) {
        int s = g_ssrc[j];
        float w = __expf(lrelu(g_as1[s * 8 + h] + ad));
        acc8h(*(const uint4*)(g_h1h + s * F1 + h * 8), w, acc0, acc1);
        ws += w;
    }

    // normalize + bias + ELU (thread h owns features [8h, 8h+8))
    float r = __fdividef(1.f, ws);
    float4 bb0 = *(const float4*)(b1 + h * 8);
    float4 bb1 = *(const float4*)(b1 + h * 8 + 4);
    float o[8];
    o[0] = acc0.x * r + bb0.x; o[1] = acc0.y * r + bb0.y;
    o[2] = acc0.z * r + bb0.z; o[3] = acc0.w * r + bb0.w;
    o[4] = acc1.x * r + bb1.x; o[5] = acc1.y * r + bb1.y;
    o[6] = acc1.z * r + bb1.z; o[7] = acc1.w * r + bb1.w;
#pragma unroll
    for (int i = 0; i < 8; i++) o[i] = o[i] > 0.f ? o[i] : expm1f(o[i]);

    // fused layer-2 gemm: partials over this thread's 8 features
    float p[DIM];
#pragma unroll
    for (int c = 0; c < DIM; c++) {
        float t = 0.f;
#pragma unroll
        for (int i = 0; i < 8; i++) t += o[i] * sW2[(h * 8 + i) * DIM + c];
        p[c] = t;
    }
#pragma unroll
    for (int m = 1; m < 8; m <<= 1) {
#pragma unroll
        for (int c = 0; c < DIM; c++)
            p[c] += __shfl_xor_sync(0xffffffffu, p[c], m, 8);
    }

    if (h == 0) {
        float as2 = 0.f, ad2 = 0.f;
#pragma unroll
        for (int c = 0; c < DIM; c++) { as2 += p[c] * sS2[c]; ad2 += p[c] * sD2[c]; }
        // packed record: 8 fp16 h2 + fp32 as2
        uint4 hp;
        __half2 q0 = __floats2half2_rn(p[0], p[1]);
        __half2 q1 = __floats2half2_rn(p[2], p[3]);
        __half2 q2 = __floats2half2_rn(p[4], p[5]);
        __half2 q3 = __floats2half2_rn(p[6], p[7]);
        hp.x = *(unsigned*)&q0; hp.y = *(unsigned*)&q1;
        hp.z = *(unsigned*)&q2; hp.w = *(unsigned*)&q3;
        unsigned* rec = g_p2 + node * 8;
        *(uint4*)rec = hp;
        rec[4] = __float_as_uint(as2);
        g_ad2[node] = ad2;
    }
}

// ------------------------- layer 2: gather + finalize -----------------------
// 4 threads per node, 2 features each; per-edge state is one 32B record.
__global__ void __launch_bounds__(256) k_gather2(const float* __restrict__ b2,
                                                 int n, float* __restrict__ out) {
    int tid = threadIdx.x;
    int node = blockIdx.x * 64 + (tid >> 2);
    int t4 = tid & 3;
    if (node >= n) return;

    int beg = g_off[node], end = g_off[node + 1];
    float ad = g_ad2[node];

    // self-loop
    const unsigned* recN = g_p2 + node * 8;
    float2 acc;
    float ws;
    {
        unsigned hw = recN[t4];
        float as = __uint_as_float(recN[4]);
        float w = __expf(lrelu(as + ad));
        float2 f = __half22float2(*(const __half2*)&hw);
        acc.x = f.x * w; acc.y = f.y * w;
        ws = w;
    }

    int j = beg;
    for (; j + 1 < end; j += 2) {
        int s0 = g_ssrc[j], s1 = g_ssrc[j + 1];
        const unsigned* r0 = g_p2 + s0 * 8;
        const unsigned* r1 = g_p2 + s1 * 8;
        unsigned hw0 = r0[t4];   float as0 = __uint_as_float(r0[4]);
        unsigned hw1 = r1[t4];   float as1v = __uint_as_float(r1[4]);
        float w0 = __expf(lrelu(as0 + ad));
        float w1 = __expf(lrelu(as1v + ad));
        float2 f0 = __half22float2(*(const __half2*)&hw0);
        float2 f1 = __half22float2(*(const __half2*)&hw1);
        acc.x += f0.x * w0 + f1.x * w1;
        acc.y += f0.y * w0 + f1.y * w1;
        ws += w0 + w1;
    }
    if (j < end) {
        int s = g_ssrc[j];
        const unsigned* rc = g_p2 + s * 8;
        unsigned hw = rc[t4];
        float as = __uint_as_float(rc[4]);
        float w = __expf(lrelu(as + ad));
        float2 f = __half22float2(*(const __half2*)&hw);
        acc.x += f.x * w; acc.y += f.y * w;
        ws += w;
    }

    float r = __fdividef(1.f, ws);
    int c = t4 * 2;
    out[node * DIM + c]     = acc.x * r + __ldg(&b2[c]);
    out[node * DIM + c + 1] = acc.y * r + __ldg(&b2[c + 1]);
}

// ------------------------- launch -----------------------------------------
extern "C" void kernel_launch(void* const* d_in, const int* in_sizes, int n_in,
                              void* d_out, int out_size) {
    const float* x   = (const float*)d_in[0];
    const void*  ei  = d_in[1];
    const float* W1  = (const float*)d_in[2];
    const float* as1 = (const float*)d_in[3];
    const float* ad1 = (const float*)d_in[4];
    const float* b1  = (const float*)d_in[5];
    const float* W2  = (const float*)d_in[6];
    const float* as2 = (const float*)d_in[7];
    const float* ad2 = (const float*)d_in[8];
    const float* b2  = (const float*)d_in[9];
    float* out = (float*)d_out;

    int n = in_sizes[0] / F_IN;
    int e = in_sizes[1] / 2;
    const int B = 256;
    auto g = [&](long long t) { return (unsigned)((t + B - 1) / B); };
    int ntiles = (n + TILE - 1) / TILE;

    // CSR build
    k_zero    <<<g(n), B>>>((const unsigned long long*)ei, n);
    k_hist    <<<g(e), B>>>(ei, e);
    k_tilesum <<<ntiles, B>>>(n);
    k_scanb   <<<1, 128>>>(ntiles, n, e);
    k_offsets <<<ntiles, B>>>(n);
    k_scatter <<<g(e), B>>>(ei, e);

    // layer 1 (+ fused layer-2 gemm/logits)
    k_l1        <<<(n + 3) / 4, B>>>(x, W1, as1, ad1, n);
    k_gather1l2 <<<(n + 31) / 32, B>>>(b1, W2, as2, ad2, n);

    // layer 2 gather + finalize
    k_gather2   <<<(n + 63) / 64, B>>>(b2, n, out);
}